// round 5
// baseline (speedup 1.0000x reference)
#include <cuda_runtime.h>
#include <cuda_bf16.h>
#include <cstdint>

// Problem constants: B=8, N=2048, D=DQ=DV=1024
#define BATCH 8
#define SEQ   2048
#define DIM   1024
#define ROWS  (BATCH * SEQ)        // 16384

// ---------------------------------------------------------------------------
// Device scratch
// ---------------------------------------------------------------------------
__device__ __nv_bfloat16 g_xhi[(size_t)ROWS * DIM];
__device__ __nv_bfloat16 g_xlo[(size_t)ROWS * DIM];
__device__ __nv_bfloat16 g_Wqthi[(size_t)DIM * DIM], g_Wqtlo[(size_t)DIM * DIM];
__device__ __nv_bfloat16 g_Wkthi[(size_t)DIM * DIM], g_Wktlo[(size_t)DIM * DIM];
__device__ __nv_bfloat16 g_Wvthi[(size_t)DIM * DIM], g_Wvtlo[(size_t)DIM * DIM];
__device__ __nv_bfloat16 g_Qhi[(size_t)ROWS * DIM], g_Qlo[(size_t)ROWS * DIM];
__device__ __nv_bfloat16 g_Khi[(size_t)ROWS * DIM], g_Klo[(size_t)ROWS * DIM];
__device__ __nv_bfloat16 g_Vthi[(size_t)BATCH * DIM * SEQ], g_Vtlo[(size_t)BATCH * DIM * SEQ];
__device__ __nv_bfloat16 g_Phi[(size_t)BATCH * SEQ * SEQ], g_Plo[(size_t)BATCH * SEQ * SEQ];
__device__ float g_rowsum[(size_t)ROWS];

// ---------------------------------------------------------------------------
// PTX helpers (portable sm_80+: mma.sync / ldmatrix / cp.async)
// ---------------------------------------------------------------------------
__device__ __forceinline__ uint32_t smem_to_u32(const void* p) {
    uint32_t a;
    asm("{ .reg .u64 t; cvta.to.shared.u64 t, %1; cvt.u32.u64 %0, t; }" : "=r"(a) : "l"(p));
    return a;
}
__device__ __forceinline__ void cp16(uint32_t dst, const void* src) {
    asm volatile("cp.async.cg.shared.global [%0], [%1], 16;" :: "r"(dst), "l"(src));
}
#define CP_COMMIT() asm volatile("cp.async.commit_group;" ::: "memory")
#define CP_WAIT1()  asm volatile("cp.async.wait_group 1;" ::: "memory")

__device__ __forceinline__ void ldsm_x4(uint32_t* r, uint32_t addr) {
    asm volatile("ldmatrix.sync.aligned.m8n8.x4.shared.b16 {%0,%1,%2,%3}, [%4];"
        : "=r"(r[0]), "=r"(r[1]), "=r"(r[2]), "=r"(r[3]) : "r"(addr));
}
__device__ __forceinline__ void mma16816(float* d, const uint32_t* a, const uint32_t* b) {
    asm volatile("mma.sync.aligned.m16n8k16.row.col.f32.bf16.bf16.f32 "
        "{%0,%1,%2,%3}, {%4,%5,%6,%7}, {%8,%9}, {%0,%1,%2,%3};"
        : "+f"(d[0]), "+f"(d[1]), "+f"(d[2]), "+f"(d[3])
        : "r"(a[0]), "r"(a[1]), "r"(a[2]), "r"(a[3]), "r"(b[0]), "r"(b[1]));
}
__device__ __forceinline__ void split2(float a, float b, uint32_t& hi2, uint32_t& lo2) {
    __nv_bfloat16 ha = __float2bfloat16(a);
    __nv_bfloat16 hb = __float2bfloat16(b);
    __nv_bfloat16 la = __float2bfloat16(a - __bfloat162float(ha));
    __nv_bfloat16 lb = __float2bfloat16(b - __bfloat162float(hb));
    __nv_bfloat162 h; h.x = ha; h.y = hb;
    __nv_bfloat162 l; l.x = la; l.y = lb;
    hi2 = *(uint32_t*)&h;
    lo2 = *(uint32_t*)&l;
}

// ---------------------------------------------------------------------------
// mma.sync GEMM, 128x128 block tile, K-chunk 32, 3-stage cp.async pipeline,
// 8 warps (4x2), warp tile 32x64, term-major MMA ordering.
// EPI: 1 = split hi/lo bf16 out (+bias)
//      2 = TRANSPOSED split hi/lo bf16 out (V^T), smem-staged (+bias)
//      3 = exp + split hi/lo bf16 out + atomic per-row sums (scores)
//      4 = fp32 out divided by rowsum (attn output)
// ---------------------------------------------------------------------------
#define SPAD   40
#define SPAD2  (SPAD * 2)                // 80 B per smem row
#define TILEB  (128 * SPAD2)             // 10240 B
#define STAGEB (4 * TILEB)               // 40960 B  (Ahi, Alo, Bhi, Blo)
#define NSTAGE 3
#define GEMM_SMEM (NSTAGE * STAGEB)      // 122880 B

template<int EPI, bool HASBIAS>
__global__ __launch_bounds__(256)
void gemm_mma(const __nv_bfloat16* __restrict__ Ahi, const __nv_bfloat16* __restrict__ Alo,
              const __nv_bfloat16* __restrict__ Bhi, const __nv_bfloat16* __restrict__ Blo,
              const float* __restrict__ bias,
              float* __restrict__ Cf,
              __nv_bfloat16* __restrict__ Chi, __nv_bfloat16* __restrict__ Clo,
              float* __restrict__ rs,
              int M, int N, int K,
              long long sA, long long sB, long long sC)
{
    extern __shared__ char smem[];
    const uint32_t sbase = smem_to_u32(smem);

    const int tid = threadIdx.x;
    const int wid = tid >> 5;
    const int lid = tid & 31;
    const int wm  = wid & 3;
    const int wn  = wid >> 2;
    const int rowBase = blockIdx.y * 128;
    const int colBase = blockIdx.x * 128;
    const int z = blockIdx.z;

    const __nv_bfloat16* As[2] = { Ahi + (long long)z * sA, Alo + (long long)z * sA };
    const __nv_bfloat16* Bs[2] = { Bhi + (long long)z * sB, Blo + (long long)z * sB };

    const int seg0row = (tid * 2) >> 2, seg0c = (tid * 2) & 3;
    const int seg1row = (tid * 2 + 1) >> 2, seg1c = (tid * 2 + 1) & 3;

    auto load_chunk = [&](int c, int stage) {
        const uint32_t st = sbase + stage * STAGEB;
        const long long kOff = (long long)c * 32;
#pragma unroll
        for (int t = 0; t < 4; ++t) {
            const __nv_bfloat16* src = (t < 2) ? As[t] : Bs[t - 2];
            const int rB = (t < 2) ? rowBase : colBase;
            const uint32_t tb = st + t * TILEB;
            cp16(tb + seg0row * SPAD2 + seg0c * 16,
                 src + (long long)(rB + seg0row) * K + kOff + seg0c * 8);
            cp16(tb + seg1row * SPAD2 + seg1c * 16,
                 src + (long long)(rB + seg1row) * K + kOff + seg1c * 8);
        }
        CP_COMMIT();
    };

    float acc[2][8][4];
#pragma unroll
    for (int i = 0; i < 2; ++i)
#pragma unroll
        for (int j = 0; j < 8; ++j)
#pragma unroll
            for (int q = 0; q < 4; ++q) acc[i][j][q] = 0.0f;

    const uint32_t aRowOff = (uint32_t)(lid & 15) * SPAD2 + (uint32_t)(lid >> 4) * 16;
    const uint32_t bRowOff = ((uint32_t)(lid & 7) + ((uint32_t)(lid >> 4) & 1) * 8) * SPAD2
                           + (((uint32_t)(lid >> 3) & 1)) * 16;

    const int nChunks = K >> 5;

    // Prefetch stages 0 and 1
    load_chunk(0, 0);
    if (nChunks > 1) load_chunk(1, 1); else CP_COMMIT();

    int stage = 0;
    for (int c = 0; c < nChunks; ++c) {
        CP_WAIT1();              // chunk c resident
        __syncthreads();         // all warps done with the stage about to be overwritten

        // prefetch chunk c+2 into stage (stage+2)%3 (empty commit keeps group count)
        {
            int ps = stage + 2; if (ps >= NSTAGE) ps -= NSTAGE;
            if (c + 2 < nChunks) load_chunk(c + 2, ps); else CP_COMMIT();
        }

        const uint32_t st = sbase + stage * STAGEB;
        const uint32_t aHiB = st + 0 * TILEB + (uint32_t)(wm * 32) * SPAD2 + aRowOff;
        const uint32_t aLoB = st + 1 * TILEB + (uint32_t)(wm * 32) * SPAD2 + aRowOff;
        const uint32_t bHiB = st + 2 * TILEB + (uint32_t)(wn * 64) * SPAD2 + bRowOff;
        const uint32_t bLoB = st + 3 * TILEB + (uint32_t)(wn * 64) * SPAD2 + bRowOff;

#pragma unroll
        for (int k16 = 0; k16 < 2; ++k16) {
            const uint32_t kb = (uint32_t)(k16 * 32);
            uint32_t ah[2][4], al[2][4], bh[8][2], bl[8][2];
            ldsm_x4(ah[0], aHiB + kb);
            ldsm_x4(ah[1], aHiB + kb + 16 * SPAD2);
            ldsm_x4(al[0], aLoB + kb);
            ldsm_x4(al[1], aLoB + kb + 16 * SPAD2);
#pragma unroll
            for (int p = 0; p < 4; ++p) {
                uint32_t r[4];
                ldsm_x4(r, bHiB + kb + (uint32_t)(p * 16) * SPAD2);
                bh[p * 2][0] = r[0]; bh[p * 2][1] = r[1];
                bh[p * 2 + 1][0] = r[2]; bh[p * 2 + 1][1] = r[3];
                ldsm_x4(r, bLoB + kb + (uint32_t)(p * 16) * SPAD2);
                bl[p * 2][0] = r[0]; bl[p * 2][1] = r[1];
                bl[p * 2 + 1][0] = r[2]; bl[p * 2 + 1][1] = r[3];
            }
            // term-major: no back-to-back RAW on any accumulator
#pragma unroll
            for (int i = 0; i < 2; ++i)
#pragma unroll
                for (int j = 0; j < 8; ++j) mma16816(acc[i][j], ah[i], bh[j]);
#pragma unroll
            for (int i = 0; i < 2; ++i)
#pragma unroll
                for (int j = 0; j < 8; ++j) mma16816(acc[i][j], ah[i], bl[j]);
#pragma unroll
            for (int i = 0; i < 2; ++i)
#pragma unroll
                for (int j = 0; j < 8; ++j) mma16816(acc[i][j], al[i], bh[j]);
        }
        if (++stage >= NSTAGE) stage = 0;
    }

    // ---------------- epilogues ----------------
    const int g = lid >> 2, t = lid & 3;

    if (EPI == 1) {
        // split hi/lo bf16 output, row-major [M,N]
#pragma unroll
        for (int i = 0; i < 2; ++i) {
            const int r0 = rowBase + wm * 32 + i * 16 + g;
            const int r1 = r0 + 8;
#pragma unroll
            for (int j = 0; j < 8; ++j) {
                const int col = colBase + wn * 64 + j * 8 + t * 2;
                float b0 = 0.f, b1 = 0.f;
                if (HASBIAS) { b0 = __ldg(bias + col); b1 = __ldg(bias + col + 1); }
                uint32_t h2, l2;
                split2(acc[i][j][0] + b0, acc[i][j][1] + b1, h2, l2);
                *(uint32_t*)(Chi + (long long)r0 * N + col) = h2;
                *(uint32_t*)(Clo + (long long)r0 * N + col) = l2;
                split2(acc[i][j][2] + b0, acc[i][j][3] + b1, h2, l2);
                *(uint32_t*)(Chi + (long long)r1 * N + col) = h2;
                *(uint32_t*)(Clo + (long long)r1 * N + col) = l2;
            }
        }
    } else if (EPI == 2) {
        // transposed split output Vt[DIM, SEQ] per batch, smem-staged
        __syncthreads();
        float* buf = (float*)smem;
#pragma unroll
        for (int i = 0; i < 2; ++i) {
            const int lr = wm * 32 + i * 16 + g;
#pragma unroll
            for (int j = 0; j < 8; ++j) {
                const int lc = wn * 64 + j * 8 + t * 2;
                float b0 = 0.f, b1 = 0.f;
                if (HASBIAS) {
                    b0 = __ldg(bias + colBase + lc);
                    b1 = __ldg(bias + colBase + lc + 1);
                }
                buf[lr * 129 + lc]           = acc[i][j][0] + b0;
                buf[lr * 129 + lc + 1]       = acc[i][j][1] + b1;
                buf[(lr + 8) * 129 + lc]     = acc[i][j][2] + b0;
                buf[(lr + 8) * 129 + lc + 1] = acc[i][j][3] + b1;
            }
        }
        __syncthreads();
        const int dcol = tid >> 1;
        const int sb2  = (tid & 1) * 64;
        const int bIdx = rowBase >> 11;
        const int srow0 = rowBase & (SEQ - 1);
        long long o = (long long)bIdx * DIM * SEQ + (long long)(colBase + dcol) * SEQ
                    + srow0 + sb2;
        __nv_bfloat16* Hb = Chi + o;
        __nv_bfloat16* Lb = Clo + o;
#pragma unroll
        for (int s2 = 0; s2 < 64; s2 += 2) {
            float v0 = buf[(sb2 + s2) * 129 + dcol];
            float v1 = buf[(sb2 + s2 + 1) * 129 + dcol];
            uint32_t h2, l2;
            split2(v0, v1, h2, l2);
            *(uint32_t*)(Hb + s2) = h2;
            *(uint32_t*)(Lb + s2) = l2;
        }
    } else if (EPI == 3) {
        // scores: e = exp(s) (max-free), split to Phi/Plo, atomic per-row sums
        __nv_bfloat16* Hb = Chi + (long long)z * sC;
        __nv_bfloat16* Lb = Clo + (long long)z * sC;
#pragma unroll
        for (int i = 0; i < 2; ++i) {
            const int r0 = rowBase + wm * 32 + i * 16 + g;
            const int r1 = r0 + 8;
            float sum0 = 0.f, sum1 = 0.f;
#pragma unroll
            for (int j = 0; j < 8; ++j) {
                const int col = colBase + wn * 64 + j * 8 + t * 2;
                float e00 = __expf(acc[i][j][0]);
                float e01 = __expf(acc[i][j][1]);
                float e10 = __expf(acc[i][j][2]);
                float e11 = __expf(acc[i][j][3]);
                sum0 += e00 + e01;
                sum1 += e10 + e11;
                uint32_t h2, l2;
                split2(e00, e01, h2, l2);
                *(uint32_t*)(Hb + (long long)r0 * N + col) = h2;
                *(uint32_t*)(Lb + (long long)r0 * N + col) = l2;
                split2(e10, e11, h2, l2);
                *(uint32_t*)(Hb + (long long)r1 * N + col) = h2;
                *(uint32_t*)(Lb + (long long)r1 * N + col) = l2;
            }
            // reduce across the 4 lanes of the quad (same row)
            sum0 += __shfl_xor_sync(0xffffffffu, sum0, 1);
            sum0 += __shfl_xor_sync(0xffffffffu, sum0, 2);
            sum1 += __shfl_xor_sync(0xffffffffu, sum1, 1);
            sum1 += __shfl_xor_sync(0xffffffffu, sum1, 2);
            if (t == 0) {
                atomicAdd(rs + (long long)z * SEQ + r0, sum0);
                atomicAdd(rs + (long long)z * SEQ + r1, sum1);
            }
        }
    } else {
        // EPI == 4: fp32 output divided by rowsum
        float* C_b = Cf + (long long)z * sC;
#pragma unroll
        for (int i = 0; i < 2; ++i) {
            const int r0 = rowBase + wm * 32 + i * 16 + g;
            const int r1 = r0 + 8;
            const float inv0 = 1.0f / __ldg(rs + (long long)z * SEQ + r0);
            const float inv1 = 1.0f / __ldg(rs + (long long)z * SEQ + r1);
#pragma unroll
            for (int j = 0; j < 8; ++j) {
                const int col = colBase + wn * 64 + j * 8 + t * 2;
                *(float2*)(C_b + (long long)r0 * N + col) =
                    make_float2(acc[i][j][0] * inv0, acc[i][j][1] * inv0);
                *(float2*)(C_b + (long long)r1 * N + col) =
                    make_float2(acc[i][j][2] * inv1, acc[i][j][3] * inv1);
            }
        }
    }
}

// ---------------------------------------------------------------------------
__global__ __launch_bounds__(256)
void zero_kernel(float* __restrict__ p, int n)
{
    int i = blockIdx.x * 256 + threadIdx.x;
    if (i < n) p[i] = 0.0f;
}

// Split fp32 -> (hi, lo) bf16 (x only)
__global__ __launch_bounds__(256)
void split_kernel(const float4* __restrict__ in, uint2* __restrict__ hi, uint2* __restrict__ lo,
                  long long n4)
{
    long long i = (long long)blockIdx.x * 256 + threadIdx.x;
    if (i >= n4) return;
    float4 v = in[i];
    uint32_t h01, l01, h23, l23;
    split2(v.x, v.y, h01, l01);
    split2(v.z, v.w, h23, l23);
    uint2 ho, lo2;
    ho.x = h01; ho.y = h23;
    lo2.x = l01; lo2.y = l23;
    hi[i] = ho;
    lo[i] = lo2;
}

// Transpose fp32 [R,C] -> bf16 hi/lo [C,R] (weights)
__global__ __launch_bounds__(256)
void transpose_split_kernel(const float* __restrict__ in,
                            __nv_bfloat16* __restrict__ hi, __nv_bfloat16* __restrict__ lo,
                            int R, int C)
{
    __shared__ float t[32][33];
    const int tx = threadIdx.x, ty = threadIdx.y;
    const int x = blockIdx.x * 32 + tx;
    const int y0 = blockIdx.y * 32;
#pragma unroll
    for (int j = 0; j < 4; ++j)
        t[ty + j * 8][tx] = in[(long long)(y0 + ty + j * 8) * C + x];
    __syncthreads();

    const int ox = blockIdx.y * 32 + tx;
    const int oy0 = blockIdx.x * 32;
#pragma unroll
    for (int j = 0; j < 4; ++j) {
        float v = t[tx][ty + j * 8];
        __nv_bfloat16 h = __float2bfloat16(v);
        __nv_bfloat16 l = __float2bfloat16(v - __bfloat162float(h));
        long long o = (long long)(oy0 + ty + j * 8) * R + ox;
        hi[o] = h;
        lo[o] = l;
    }
}

// ---------------------------------------------------------------------------
extern "C" void kernel_launch(void* const* d_in, const int* in_sizes, int n_in,
                              void* d_out, int out_size)
{
    const float* x  = (const float*)d_in[0];
    const float* Wq = (const float*)d_in[1];
    const float* bq = (const float*)d_in[2];
    const float* Wk = (const float*)d_in[3];
    const float* bk = (const float*)d_in[4];
    const float* Wv = (const float*)d_in[5];
    const float* bv = (const float*)d_in[6];
    float* out = (float*)d_out;

    __nv_bfloat16 *xhi, *xlo, *Wqthi, *Wqtlo, *Wkthi, *Wktlo, *Wvthi, *Wvtlo;
    __nv_bfloat16 *Qhi, *Qlo, *Khi, *Klo, *Vthi, *Vtlo, *Phi, *Plo;
    float *rs;
    cudaGetSymbolAddress((void**)&xhi, g_xhi);     cudaGetSymbolAddress((void**)&xlo, g_xlo);
    cudaGetSymbolAddress((void**)&Wqthi, g_Wqthi); cudaGetSymbolAddress((void**)&Wqtlo, g_Wqtlo);
    cudaGetSymbolAddress((void**)&Wkthi, g_Wkthi); cudaGetSymbolAddress((void**)&Wktlo, g_Wktlo);
    cudaGetSymbolAddress((void**)&Wvthi, g_Wvthi); cudaGetSymbolAddress((void**)&Wvtlo, g_Wvtlo);
    cudaGetSymbolAddress((void**)&Qhi, g_Qhi); cudaGetSymbolAddress((void**)&Qlo, g_Qlo);
    cudaGetSymbolAddress((void**)&Khi, g_Khi); cudaGetSymbolAddress((void**)&Klo, g_Klo);
    cudaGetSymbolAddress((void**)&Vthi, g_Vthi); cudaGetSymbolAddress((void**)&Vtlo, g_Vtlo);
    cudaGetSymbolAddress((void**)&Phi, g_Phi); cudaGetSymbolAddress((void**)&Plo, g_Plo);
    cudaGetSymbolAddress((void**)&rs, g_rowsum);

    cudaFuncSetAttribute(gemm_mma<1, true>,  cudaFuncAttributeMaxDynamicSharedMemorySize, GEMM_SMEM);
    cudaFuncSetAttribute(gemm_mma<2, true>,  cudaFuncAttributeMaxDynamicSharedMemorySize, GEMM_SMEM);
    cudaFuncSetAttribute(gemm_mma<3, false>, cudaFuncAttributeMaxDynamicSharedMemorySize, GEMM_SMEM);
    cudaFuncSetAttribute(gemm_mma<4, false>, cudaFuncAttributeMaxDynamicSharedMemorySize, GEMM_SMEM);

    dim3 tblk(32, 8);

    // 0) zero rowsums
    zero_kernel<<<(ROWS + 255) / 256, 256>>>(rs, ROWS);
    // 1) Split x
    {
        long long n4 = (long long)ROWS * DIM / 4;
        split_kernel<<<(unsigned)((n4 + 255) / 256), 256>>>((const float4*)x, (uint2*)xhi, (uint2*)xlo, n4);
    }
    // 2) Transpose+split weights
    transpose_split_kernel<<<dim3(DIM / 32, DIM / 32), tblk>>>(Wq, Wqthi, Wqtlo, DIM, DIM);
    transpose_split_kernel<<<dim3(DIM / 32, DIM / 32), tblk>>>(Wk, Wkthi, Wktlo, DIM, DIM);
    transpose_split_kernel<<<dim3(DIM / 32, DIM / 32), tblk>>>(Wv, Wvthi, Wvtlo, DIM, DIM);

    // 3) Projections with fused split epilogues
    {
        dim3 g(DIM / 128, ROWS / 128, 1);
        gemm_mma<1, true><<<g, 256, GEMM_SMEM>>>(xhi, xlo, Wqthi, Wqtlo, bq,
                                                 nullptr, Qhi, Qlo, nullptr, ROWS, DIM, DIM, 0, 0, 0);
        gemm_mma<1, true><<<g, 256, GEMM_SMEM>>>(xhi, xlo, Wkthi, Wktlo, bk,
                                                 nullptr, Khi, Klo, nullptr, ROWS, DIM, DIM, 0, 0, 0);
        gemm_mma<2, true><<<g, 256, GEMM_SMEM>>>(xhi, xlo, Wvthi, Wvtlo, bv,
                                                 nullptr, Vthi, Vtlo, nullptr, ROWS, DIM, DIM, 0, 0, 0);
    }
    // 4) Scores with fused exp + split + rowsum: Phi/Plo = exp(Q K^T) (unnormalized)
    {
        dim3 g(SEQ / 128, SEQ / 128, BATCH);
        gemm_mma<3, false><<<g, 256, GEMM_SMEM>>>(Qhi, Qlo, Khi, Klo, nullptr,
                                                  nullptr, Phi, Plo, rs, SEQ, SEQ, DIM,
                                                  (long long)SEQ * DIM, (long long)SEQ * DIM,
                                                  (long long)SEQ * SEQ);
    }
    // 5) Out: out[b] = (E[b] @ V[b]) / rowsum
    {
        dim3 g(DIM / 128, SEQ / 128, BATCH);
        gemm_mma<4, false><<<g, 256, GEMM_SMEM>>>(Phi, Plo, Vthi, Vtlo, nullptr,
                                                  out, nullptr, nullptr, rs, SEQ, DIM, SEQ,
                                                  (long long)SEQ * SEQ, (long long)DIM * SEQ,
                                                  (long long)SEQ * DIM);
    }
}

// round 6
// speedup vs baseline: 1.1769x; 1.1769x over previous
#include <cuda_runtime.h>
#include <cuda_bf16.h>
#include <cstdint>

// Problem constants: B=8, N=2048, D=DQ=DV=1024
#define BATCH 8
#define SEQ   2048
#define DIM   1024
#define ROWS  (BATCH * SEQ)        // 16384

// ---------------------------------------------------------------------------
// Device scratch
// ---------------------------------------------------------------------------
__device__ __nv_bfloat16 g_xhi[(size_t)ROWS * DIM];
__device__ __nv_bfloat16 g_xlo[(size_t)ROWS * DIM];
__device__ __nv_bfloat16 g_Wqthi[(size_t)DIM * DIM], g_Wqtlo[(size_t)DIM * DIM];
__device__ __nv_bfloat16 g_Wkthi[(size_t)DIM * DIM], g_Wktlo[(size_t)DIM * DIM];
__device__ __nv_bfloat16 g_Wvthi[(size_t)DIM * DIM], g_Wvtlo[(size_t)DIM * DIM];
__device__ __nv_bfloat16 g_Qhi[(size_t)ROWS * DIM], g_Qlo[(size_t)ROWS * DIM];
__device__ __nv_bfloat16 g_Khi[(size_t)ROWS * DIM], g_Klo[(size_t)ROWS * DIM];
__device__ __nv_bfloat16 g_Vthi[(size_t)BATCH * DIM * SEQ], g_Vtlo[(size_t)BATCH * DIM * SEQ];
__device__ __nv_bfloat16 g_Phi[(size_t)BATCH * SEQ * SEQ], g_Plo[(size_t)BATCH * SEQ * SEQ];
__device__ float g_rowsum[(size_t)ROWS];

// ---------------------------------------------------------------------------
// PTX helpers (portable sm_80+: mma.sync / ldmatrix / cp.async)
// ---------------------------------------------------------------------------
__device__ __forceinline__ uint32_t smem_to_u32(const void* p) {
    uint32_t a;
    asm("{ .reg .u64 t; cvta.to.shared.u64 t, %1; cvt.u32.u64 %0, t; }" : "=r"(a) : "l"(p));
    return a;
}
__device__ __forceinline__ void cp16(uint32_t dst, const void* src) {
    asm volatile("cp.async.cg.shared.global [%0], [%1], 16;" :: "r"(dst), "l"(src));
}
#define CP_COMMIT() asm volatile("cp.async.commit_group;" ::: "memory")
#define CP_WAIT0()  asm volatile("cp.async.wait_group 0;" ::: "memory")

__device__ __forceinline__ void ldsm_x4(uint32_t* r, uint32_t addr) {
    asm volatile("ldmatrix.sync.aligned.m8n8.x4.shared.b16 {%0,%1,%2,%3}, [%4];"
        : "=r"(r[0]), "=r"(r[1]), "=r"(r[2]), "=r"(r[3]) : "r"(addr));
}
__device__ __forceinline__ void mma16816(float* d, const uint32_t* a, const uint32_t* b) {
    asm volatile("mma.sync.aligned.m16n8k16.row.col.f32.bf16.bf16.f32 "
        "{%0,%1,%2,%3}, {%4,%5,%6,%7}, {%8,%9}, {%0,%1,%2,%3};"
        : "+f"(d[0]), "+f"(d[1]), "+f"(d[2]), "+f"(d[3])
        : "r"(a[0]), "r"(a[1]), "r"(a[2]), "r"(a[3]), "r"(b[0]), "r"(b[1]));
}
__device__ __forceinline__ void split2(float a, float b, uint32_t& hi2, uint32_t& lo2) {
    __nv_bfloat16 ha = __float2bfloat16(a);
    __nv_bfloat16 hb = __float2bfloat16(b);
    __nv_bfloat16 la = __float2bfloat16(a - __bfloat162float(ha));
    __nv_bfloat16 lb = __float2bfloat16(b - __bfloat162float(hb));
    __nv_bfloat162 h; h.x = ha; h.y = hb;
    __nv_bfloat162 l; l.x = la; l.y = lb;
    hi2 = *(uint32_t*)&h;
    lo2 = *(uint32_t*)&l;
}

// ---------------------------------------------------------------------------
// mma.sync GEMM: 128x128 block tile, K-chunk 32, 2-stage cp.async (R4-proven),
// 8 warps (4x2), warp 32x64, occupancy 2 via __launch_bounds__(256,2).
// MMA order: distance-4 accumulator reuse within each p-group (12 MMAs).
// EPI: 1 = split hi/lo bf16 out (+bias)
//      2 = TRANSPOSED split hi/lo bf16 out (V^T), smem-staged (+bias)
//      3 = exp + split hi/lo bf16 out + atomic per-row sums (scores)
//      4 = fp32 out divided by rowsum (attn output)
// ---------------------------------------------------------------------------
#define SPAD   40
#define SPAD2  (SPAD * 2)                // 80 B per smem row
#define TILEB  (128 * SPAD2)             // 10240 B
#define STAGEB (4 * TILEB)               // 40960 B  (Ahi, Alo, Bhi, Blo)
#define GEMM_SMEM (2 * STAGEB)           // 81920 B

template<int EPI, bool HASBIAS>
__global__ __launch_bounds__(256, 2)
void gemm_mma(const __nv_bfloat16* __restrict__ Ahi, const __nv_bfloat16* __restrict__ Alo,
              const __nv_bfloat16* __restrict__ Bhi, const __nv_bfloat16* __restrict__ Blo,
              const float* __restrict__ bias,
              float* __restrict__ Cf,
              __nv_bfloat16* __restrict__ Chi, __nv_bfloat16* __restrict__ Clo,
              float* __restrict__ rs,
              int M, int N, int K,
              long long sA, long long sB, long long sC)
{
    extern __shared__ char smem[];
    const uint32_t sbase = smem_to_u32(smem);

    const int tid = threadIdx.x;
    const int wid = tid >> 5;
    const int lid = tid & 31;
    const int wm  = wid & 3;
    const int wn  = wid >> 2;
    const int rowBase = blockIdx.y * 128;
    const int colBase = blockIdx.x * 128;
    const int z = blockIdx.z;

    const __nv_bfloat16* As[2] = { Ahi + (long long)z * sA, Alo + (long long)z * sA };
    const __nv_bfloat16* Bs[2] = { Bhi + (long long)z * sB, Blo + (long long)z * sB };

    const int seg0row = (tid * 2) >> 2, seg0c = (tid * 2) & 3;
    const int seg1row = (tid * 2 + 1) >> 2, seg1c = (tid * 2 + 1) & 3;

    auto load_chunk = [&](int c, int stage) {
        const uint32_t st = sbase + stage * STAGEB;
        const long long kOff = (long long)c * 32;
#pragma unroll
        for (int t = 0; t < 4; ++t) {
            const __nv_bfloat16* src = (t < 2) ? As[t] : Bs[t - 2];
            const int rB = (t < 2) ? rowBase : colBase;
            const uint32_t tb = st + t * TILEB;
            cp16(tb + seg0row * SPAD2 + seg0c * 16,
                 src + (long long)(rB + seg0row) * K + kOff + seg0c * 8);
            cp16(tb + seg1row * SPAD2 + seg1c * 16,
                 src + (long long)(rB + seg1row) * K + kOff + seg1c * 8);
        }
        CP_COMMIT();
    };

    float acc[2][8][4];
#pragma unroll
    for (int i = 0; i < 2; ++i)
#pragma unroll
        for (int j = 0; j < 8; ++j)
#pragma unroll
            for (int q = 0; q < 4; ++q) acc[i][j][q] = 0.0f;

    const uint32_t aRowOff = (uint32_t)(lid & 15) * SPAD2 + (uint32_t)(lid >> 4) * 16;
    const uint32_t bRowOff = ((uint32_t)(lid & 7) + ((uint32_t)(lid >> 4) & 1) * 8) * SPAD2
                           + (((uint32_t)(lid >> 3) & 1)) * 16;

    const int nChunks = K >> 5;
    load_chunk(0, 0);

    for (int c = 0; c < nChunks; ++c) {
        const int s = c & 1;
        CP_WAIT0();
        __syncthreads();
        if (c + 1 < nChunks) load_chunk(c + 1, s ^ 1);

        const uint32_t st = sbase + s * STAGEB;
        const uint32_t aHiB = st + 0 * TILEB + (uint32_t)(wm * 32) * SPAD2 + aRowOff;
        const uint32_t aLoB = st + 1 * TILEB + (uint32_t)(wm * 32) * SPAD2 + aRowOff;
        const uint32_t bHiB = st + 2 * TILEB + (uint32_t)(wn * 64) * SPAD2 + bRowOff;
        const uint32_t bLoB = st + 3 * TILEB + (uint32_t)(wn * 64) * SPAD2 + bRowOff;

#pragma unroll
        for (int k16 = 0; k16 < 2; ++k16) {
            const uint32_t kb = (uint32_t)(k16 * 32);
            uint32_t ah[2][4], al[2][4];
            ldsm_x4(ah[0], aHiB + kb);
            ldsm_x4(ah[1], aHiB + kb + 16 * SPAD2);
            ldsm_x4(al[0], aLoB + kb);
            ldsm_x4(al[1], aLoB + kb + 16 * SPAD2);
#pragma unroll
            for (int p = 0; p < 4; ++p) {
                uint32_t rh[4], rl[4];
                ldsm_x4(rh, bHiB + kb + (uint32_t)(p * 16) * SPAD2);
                ldsm_x4(rl, bLoB + kb + (uint32_t)(p * 16) * SPAD2);
                uint32_t bh0[2] = { rh[0], rh[1] }, bh1[2] = { rh[2], rh[3] };
                uint32_t bl0[2] = { rl[0], rl[1] }, bl1[2] = { rl[2], rl[3] };
                float* a00 = acc[0][p * 2];
                float* a10 = acc[1][p * 2];
                float* a01 = acc[0][p * 2 + 1];
                float* a11 = acc[1][p * 2 + 1];
                // distance-4 accumulator reuse: hh block, hl block, lh block
                mma16816(a00, ah[0], bh0);
                mma16816(a10, ah[1], bh0);
                mma16816(a01, ah[0], bh1);
                mma16816(a11, ah[1], bh1);
                mma16816(a00, ah[0], bl0);
                mma16816(a10, ah[1], bl0);
                mma16816(a01, ah[0], bl1);
                mma16816(a11, ah[1], bl1);
                mma16816(a00, al[0], bh0);
                mma16816(a10, al[1], bh0);
                mma16816(a01, al[0], bh1);
                mma16816(a11, al[1], bh1);
            }
        }
        __syncthreads();
    }

    // ---------------- epilogues ----------------
    const int g = lid >> 2, t = lid & 3;

    if (EPI == 1) {
        // split hi/lo bf16 output, row-major [M,N]
#pragma unroll
        for (int i = 0; i < 2; ++i) {
            const int r0 = rowBase + wm * 32 + i * 16 + g;
            const int r1 = r0 + 8;
#pragma unroll
            for (int j = 0; j < 8; ++j) {
                const int col = colBase + wn * 64 + j * 8 + t * 2;
                float b0 = 0.f, b1 = 0.f;
                if (HASBIAS) { b0 = __ldg(bias + col); b1 = __ldg(bias + col + 1); }
                uint32_t h2, l2;
                split2(acc[i][j][0] + b0, acc[i][j][1] + b1, h2, l2);
                *(uint32_t*)(Chi + (long long)r0 * N + col) = h2;
                *(uint32_t*)(Clo + (long long)r0 * N + col) = l2;
                split2(acc[i][j][2] + b0, acc[i][j][3] + b1, h2, l2);
                *(uint32_t*)(Chi + (long long)r1 * N + col) = h2;
                *(uint32_t*)(Clo + (long long)r1 * N + col) = l2;
            }
        }
    } else if (EPI == 2) {
        // transposed split output Vt[DIM, SEQ] per batch, smem-staged
        float* buf = (float*)smem;
#pragma unroll
        for (int i = 0; i < 2; ++i) {
            const int lr = wm * 32 + i * 16 + g;
#pragma unroll
            for (int j = 0; j < 8; ++j) {
                const int lc = wn * 64 + j * 8 + t * 2;
                float b0 = 0.f, b1 = 0.f;
                if (HASBIAS) {
                    b0 = __ldg(bias + colBase + lc);
                    b1 = __ldg(bias + colBase + lc + 1);
                }
                buf[lr * 129 + lc]           = acc[i][j][0] + b0;
                buf[lr * 129 + lc + 1]       = acc[i][j][1] + b1;
                buf[(lr + 8) * 129 + lc]     = acc[i][j][2] + b0;
                buf[(lr + 8) * 129 + lc + 1] = acc[i][j][3] + b1;
            }
        }
        __syncthreads();
        const int dcol = tid >> 1;
        const int sb2  = (tid & 1) * 64;
        const int bIdx = rowBase >> 11;
        const int srow0 = rowBase & (SEQ - 1);
        long long o = (long long)bIdx * DIM * SEQ + (long long)(colBase + dcol) * SEQ
                    + srow0 + sb2;
        __nv_bfloat16* Hb = Chi + o;
        __nv_bfloat16* Lb = Clo + o;
#pragma unroll
        for (int s2 = 0; s2 < 64; s2 += 2) {
            float v0 = buf[(sb2 + s2) * 129 + dcol];
            float v1 = buf[(sb2 + s2 + 1) * 129 + dcol];
            uint32_t h2, l2;
            split2(v0, v1, h2, l2);
            *(uint32_t*)(Hb + s2) = h2;
            *(uint32_t*)(Lb + s2) = l2;
        }
    } else if (EPI == 3) {
        // scores: e = exp(s) (max-free), split to Phi/Plo, atomic per-row sums
        __nv_bfloat16* Hb = Chi + (long long)z * sC;
        __nv_bfloat16* Lb = Clo + (long long)z * sC;
#pragma unroll
        for (int i = 0; i < 2; ++i) {
            const int r0 = rowBase + wm * 32 + i * 16 + g;
            const int r1 = r0 + 8;
            float sum0 = 0.f, sum1 = 0.f;
#pragma unroll
            for (int j = 0; j < 8; ++j) {
                const int col = colBase + wn * 64 + j * 8 + t * 2;
                float e00 = __expf(acc[i][j][0]);
                float e01 = __expf(acc[i][j][1]);
                float e10 = __expf(acc[i][j][2]);
                float e11 = __expf(acc[i][j][3]);
                sum0 += e00 + e01;
                sum1 += e10 + e11;
                uint32_t h2, l2;
                split2(e00, e01, h2, l2);
                *(uint32_t*)(Hb + (long long)r0 * N + col) = h2;
                *(uint32_t*)(Lb + (long long)r0 * N + col) = l2;
                split2(e10, e11, h2, l2);
                *(uint32_t*)(Hb + (long long)r1 * N + col) = h2;
                *(uint32_t*)(Lb + (long long)r1 * N + col) = l2;
            }
            sum0 += __shfl_xor_sync(0xffffffffu, sum0, 1);
            sum0 += __shfl_xor_sync(0xffffffffu, sum0, 2);
            sum1 += __shfl_xor_sync(0xffffffffu, sum1, 1);
            sum1 += __shfl_xor_sync(0xffffffffu, sum1, 2);
            if (t == 0) {
                atomicAdd(rs + (long long)z * SEQ + r0, sum0);
                atomicAdd(rs + (long long)z * SEQ + r1, sum1);
            }
        }
    } else {
        // EPI == 4: fp32 output divided by rowsum
        float* C_b = Cf + (long long)z * sC;
#pragma unroll
        for (int i = 0; i < 2; ++i) {
            const int r0 = rowBase + wm * 32 + i * 16 + g;
            const int r1 = r0 + 8;
            const float inv0 = 1.0f / __ldg(rs + (long long)z * SEQ + r0);
            const float inv1 = 1.0f / __ldg(rs + (long long)z * SEQ + r1);
#pragma unroll
            for (int j = 0; j < 8; ++j) {
                const int col = colBase + wn * 64 + j * 8 + t * 2;
                *(float2*)(C_b + (long long)r0 * N + col) =
                    make_float2(acc[i][j][0] * inv0, acc[i][j][1] * inv0);
                *(float2*)(C_b + (long long)r1 * N + col) =
                    make_float2(acc[i][j][2] * inv1, acc[i][j][3] * inv1);
            }
        }
    }
}

// ---------------------------------------------------------------------------
__global__ __launch_bounds__(256)
void zero_kernel(float* __restrict__ p, int n)
{
    int i = blockIdx.x * 256 + threadIdx.x;
    if (i < n) p[i] = 0.0f;
}

// Split fp32 -> (hi, lo) bf16 (x only)
__global__ __launch_bounds__(256)
void split_kernel(const float4* __restrict__ in, uint2* __restrict__ hi, uint2* __restrict__ lo,
                  long long n4)
{
    long long i = (long long)blockIdx.x * 256 + threadIdx.x;
    if (i >= n4) return;
    float4 v = in[i];
    uint32_t h01, l01, h23, l23;
    split2(v.x, v.y, h01, l01);
    split2(v.z, v.w, h23, l23);
    uint2 ho, lo2;
    ho.x = h01; ho.y = h23;
    lo2.x = l01; lo2.y = l23;
    hi[i] = ho;
    lo[i] = lo2;
}

// Transpose fp32 [R,C] -> bf16 hi/lo [C,R] (weights)
__global__ __launch_bounds__(256)
void transpose_split_kernel(const float* __restrict__ in,
                            __nv_bfloat16* __restrict__ hi, __nv_bfloat16* __restrict__ lo,
                            int R, int C)
{
    __shared__ float t[32][33];
    const int tx = threadIdx.x, ty = threadIdx.y;
    const int x = blockIdx.x * 32 + tx;
    const int y0 = blockIdx.y * 32;
#pragma unroll
    for (int j = 0; j < 4; ++j)
        t[ty + j * 8][tx] = in[(long long)(y0 + ty + j * 8) * C + x];
    __syncthreads();

    const int ox = blockIdx.y * 32 + tx;
    const int oy0 = blockIdx.x * 32;
#pragma unroll
    for (int j = 0; j < 4; ++j) {
        float v = t[tx][ty + j * 8];
        __nv_bfloat16 h = __float2bfloat16(v);
        __nv_bfloat16 l = __float2bfloat16(v - __bfloat162float(h));
        long long o = (long long)(oy0 + ty + j * 8) * R + ox;
        hi[o] = h;
        lo[o] = l;
    }
}

// ---------------------------------------------------------------------------
extern "C" void kernel_launch(void* const* d_in, const int* in_sizes, int n_in,
                              void* d_out, int out_size)
{
    const float* x  = (const float*)d_in[0];
    const float* Wq = (const float*)d_in[1];
    const float* bq = (const float*)d_in[2];
    const float* Wk = (const float*)d_in[3];
    const float* bk = (const float*)d_in[4];
    const float* Wv = (const float*)d_in[5];
    const float* bv = (const float*)d_in[6];
    float* out = (float*)d_out;

    __nv_bfloat16 *xhi, *xlo, *Wqthi, *Wqtlo, *Wkthi, *Wktlo, *Wvthi, *Wvtlo;
    __nv_bfloat16 *Qhi, *Qlo, *Khi, *Klo, *Vthi, *Vtlo, *Phi, *Plo;
    float *rs;
    cudaGetSymbolAddress((void**)&xhi, g_xhi);     cudaGetSymbolAddress((void**)&xlo, g_xlo);
    cudaGetSymbolAddress((void**)&Wqthi, g_Wqthi); cudaGetSymbolAddress((void**)&Wqtlo, g_Wqtlo);
    cudaGetSymbolAddress((void**)&Wkthi, g_Wkthi); cudaGetSymbolAddress((void**)&Wktlo, g_Wktlo);
    cudaGetSymbolAddress((void**)&Wvthi, g_Wvthi); cudaGetSymbolAddress((void**)&Wvtlo, g_Wvtlo);
    cudaGetSymbolAddress((void**)&Qhi, g_Qhi); cudaGetSymbolAddress((void**)&Qlo, g_Qlo);
    cudaGetSymbolAddress((void**)&Khi, g_Khi); cudaGetSymbolAddress((void**)&Klo, g_Klo);
    cudaGetSymbolAddress((void**)&Vthi, g_Vthi); cudaGetSymbolAddress((void**)&Vtlo, g_Vtlo);
    cudaGetSymbolAddress((void**)&Phi, g_Phi); cudaGetSymbolAddress((void**)&Plo, g_Plo);
    cudaGetSymbolAddress((void**)&rs, g_rowsum);

    cudaFuncSetAttribute(gemm_mma<1, true>,  cudaFuncAttributeMaxDynamicSharedMemorySize, GEMM_SMEM);
    cudaFuncSetAttribute(gemm_mma<2, true>,  cudaFuncAttributeMaxDynamicSharedMemorySize, GEMM_SMEM);
    cudaFuncSetAttribute(gemm_mma<3, false>, cudaFuncAttributeMaxDynamicSharedMemorySize, GEMM_SMEM);
    cudaFuncSetAttribute(gemm_mma<4, false>, cudaFuncAttributeMaxDynamicSharedMemorySize, GEMM_SMEM);

    dim3 tblk(32, 8);

    // 0) zero rowsums
    zero_kernel<<<(ROWS + 255) / 256, 256>>>(rs, ROWS);
    // 1) Split x
    {
        long long n4 = (long long)ROWS * DIM / 4;
        split_kernel<<<(unsigned)((n4 + 255) / 256), 256>>>((const float4*)x, (uint2*)xhi, (uint2*)xlo, n4);
    }
    // 2) Transpose+split weights
    transpose_split_kernel<<<dim3(DIM / 32, DIM / 32), tblk>>>(Wq, Wqthi, Wqtlo, DIM, DIM);
    transpose_split_kernel<<<dim3(DIM / 32, DIM / 32), tblk>>>(Wk, Wkthi, Wktlo, DIM, DIM);
    transpose_split_kernel<<<dim3(DIM / 32, DIM / 32), tblk>>>(Wv, Wvthi, Wvtlo, DIM, DIM);

    // 3) Projections with fused split epilogues
    {
        dim3 g(DIM / 128, ROWS / 128, 1);
        gemm_mma<1, true><<<g, 256, GEMM_SMEM>>>(xhi, xlo, Wqthi, Wqtlo, bq,
                                                 nullptr, Qhi, Qlo, nullptr, ROWS, DIM, DIM, 0, 0, 0);
        gemm_mma<1, true><<<g, 256, GEMM_SMEM>>>(xhi, xlo, Wkthi, Wktlo, bk,
                                                 nullptr, Khi, Klo, nullptr, ROWS, DIM, DIM, 0, 0, 0);
        gemm_mma<2, true><<<g, 256, GEMM_SMEM>>>(xhi, xlo, Wvthi, Wvtlo, bv,
                                                 nullptr, Vthi, Vtlo, nullptr, ROWS, DIM, DIM, 0, 0, 0);
    }
    // 4) Scores with fused exp + split + rowsum: Phi/Plo = exp(Q K^T) (unnormalized)
    {
        dim3 g(SEQ / 128, SEQ / 128, BATCH);
        gemm_mma<3, false><<<g, 256, GEMM_SMEM>>>(Qhi, Qlo, Khi, Klo, nullptr,
                                                  nullptr, Phi, Plo, rs, SEQ, SEQ, DIM,
                                                  (long long)SEQ * DIM, (long long)SEQ * DIM,
                                                  (long long)SEQ * SEQ);
    }
    // 5) Out: out[b] = (E[b] @ V[b]) / rowsum
    {
        dim3 g(DIM / 128, SEQ / 128, BATCH);
        gemm_mma<4, false><<<g, 256, GEMM_SMEM>>>(Phi, Plo, Vthi, Vtlo, nullptr,
                                                  out, nullptr, nullptr, rs, SEQ, DIM, SEQ,
                                                  (long long)SEQ * SEQ, (long long)DIM * SEQ,
                                                  (long long)SEQ * DIM);
    }
}